// round 11
// baseline (speedup 1.0000x reference)
#include <cuda_runtime.h>
#include <cuda_bf16.h>
#include <math.h>

// ---------------------------------------------------------------------------
// mLSTM cell — TM=8 GEMM + 2-chunk overlap.
//   K1: fp32 SIMT GEMM, split-K=8, BM=64/BN=64/BK=32, TM=8 x TN=4
//   K2: split-K sum + bias + pointwise gates -> m_t, n_t, scratch
//   K3: C_t = f*C_prev + add fused with Cq and h_t (single HBM pass)
// Overlap: 2 batch chunks of 64 rows; G1+K2_1 hide under K3_0's DRAM stream.
// ---------------------------------------------------------------------------

#define Bsz 128
#define Hdim 512
#define SIXH 3072
#define INV_SQRT_H 0.044194173824159216f   // 1/sqrt(512)

#define KSPLIT 8
#define KCH    64                           // K per split (512/8)
#define GSTRIDE (Bsz * SIXH)                // 393216
#define MB     64                           // batch rows per chunk

// Scratch (device globals; no allocation allowed anywhere in this file)
__device__ float g_part[KSPLIT * GSTRIDE];  // 12.6 MB split-K partials
__device__ float g_f[Bsz * Hdim];
__device__ float g_add[Bsz * Hdim];
__device__ float g_o[Bsz * Hdim];
__device__ float g_q[Bsz * Hdim];
__device__ float g_rdenom[Bsz];

// ---------------------------------------------------------------------------
// Kernel 1: tiled fp32 GEMM chunk (64 rows at m0), split-K=8 over grid.z.
// BM=64, BN=64, BK=32, 128 threads, TM=8 x TN=4 strided register tile.
// Per warp per 4-k sub-iter: 16 smem wavefronts vs 128 FFMA -> FMA-bound.
// grid per chunk = (48, 1, 8) = 384 blocks.
// ---------------------------------------------------------------------------
#define BM 64
#define BN 64
#define BK 32

__global__ __launch_bounds__(128) void gemm_kernel(
    const float* __restrict__ X,      // [128, 512]
    const float* __restrict__ W,      // [3072, 512]
    int m0)
{
    __shared__ float As[BM][BK + 4];
    __shared__ float Bs[BN][BK + 4];

    const int tid = threadIdx.x;
    const int tm = tid >> 4;          // 0..7   (m = tm + 8r, r 0..7)
    const int tn = tid & 15;          // 0..15  (n = tn + 16s, s 0..3)
    const int bn = blockIdx.x * BN;
    const int kb = blockIdx.z * KCH;

    float acc[8][4];
#pragma unroll
    for (int r = 0; r < 8; r++)
#pragma unroll
        for (int s = 0; s < 4; s++) acc[r][s] = 0.f;

    const int lm = tid >> 3;          // 0..15 (load row)
    const int lk = (tid & 7) << 2;    // 0..28 step 4

#pragma unroll
    for (int k0 = 0; k0 < KCH; k0 += BK) {
        const int kabs = kb + k0 + lk;
        // A tile: 64x32 floats, 4 x float4 per thread
#pragma unroll
        for (int i = 0; i < 4; i++)
            *(float4*)&As[lm + 16 * i][lk] =
                *(const float4*)&X[(m0 + lm + 16 * i) * 512 + kabs];
        // B tile: 64x32 floats, 4 x float4 per thread
#pragma unroll
        for (int i = 0; i < 4; i++)
            *(float4*)&Bs[lm + 16 * i][lk] =
                *(const float4*)&W[(bn + lm + 16 * i) * 512 + kabs];
        __syncthreads();

#pragma unroll
        for (int kk = 0; kk < BK; kk += 4) {
            float4 a[8], bq[4];
#pragma unroll
            for (int r = 0; r < 8; r++) a[r] = *(const float4*)&As[tm + 8 * r][kk];
#pragma unroll
            for (int s = 0; s < 4; s++) bq[s] = *(const float4*)&Bs[tn + 16 * s][kk];
#pragma unroll
            for (int r = 0; r < 8; r++)
#pragma unroll
                for (int s = 0; s < 4; s++) {
                    acc[r][s] += a[r].x * bq[s].x;
                    acc[r][s] += a[r].y * bq[s].y;
                    acc[r][s] += a[r].z * bq[s].z;
                    acc[r][s] += a[r].w * bq[s].w;
                }
        }
        __syncthreads();
    }

    float* gp = g_part + blockIdx.z * GSTRIDE;
#pragma unroll
    for (int r = 0; r < 8; r++) {
        const int m = m0 + tm + 8 * r;
#pragma unroll
        for (int s = 0; s < 4; s++) {
            const int n = bn + tn + 16 * s;
            gp[m * SIXH + n] = acc[r][s];
        }
    }
}

// ---------------------------------------------------------------------------
// Kernel 2: split-K reduction + bias + pointwise gates + per-batch denom.
// One block per batch row of the chunk. Deterministic fixed-order sum.
// ---------------------------------------------------------------------------
__global__ __launch_bounds__(512) void pointwise_kernel(
    const float* __restrict__ m_prev,
    const float* __restrict__ n_prev,
    const float* __restrict__ bias,
    float* __restrict__ out_m,
    float* __restrict__ out_n,
    int m0)
{
    __shared__ float red[512];
    const int b = m0 + blockIdx.x;
    const int h = threadIdx.x;

    float g[6];
#pragma unroll
    for (int gi = 0; gi < 6; gi++) {
        const int idx = b * SIXH + gi * Hdim + h;
        float acc = bias[gi * Hdim + h];
#pragma unroll
        for (int z = 0; z < KSPLIT; z++)
            acc += g_part[z * GSTRIDE + idx];
        g[gi] = acc;
    }
    const float ig = g[0], fg = g[1], og = g[2], qg = g[3], kg = g[4], vg = g[5];

    const int row = b * Hdim + h;
    const float mp = m_prev[row];
    const float np = n_prev[row];

    const float mt = fmaxf(fg + mp, ig);
    const float it = expf(ig - mt);
    const float ft = expf(fg + mp - mt);
    const float kt = INV_SQRT_H * kg;
    const float nt = ft * np + it * kt;
    const float ot = 1.f / (1.f + expf(-og));

    out_m[row] = mt;
    out_n[row] = nt;
    g_f[row]   = ft;
    g_add[row] = it * vg * kt;
    g_o[row]   = ot;
    g_q[row]   = qg;

    red[h] = nt * qg;
    __syncthreads();
#pragma unroll
    for (int s = 256; s > 0; s >>= 1) {
        if (h < s) red[h] += red[h + s];
        __syncthreads();
    }
    if (h == 0) g_rdenom[b] = 1.f / fmaxf(fabsf(red[0]), 1e-6f);
}

// ---------------------------------------------------------------------------
// Kernel 3: per-chunk C update. One warp per (b,i) row of 512 floats.
// Streaming hints on C (zero reuse); q rows stay L2-resident (512x reuse).
// grid per chunk = MB*Hdim/8 = 4096 blocks x 256 threads.
// ---------------------------------------------------------------------------
__global__ __launch_bounds__(256) void cupdate_kernel(
    const float* __restrict__ C_prev,
    float* __restrict__ out_C,
    float* __restrict__ out_h,
    int m0)
{
    const int row  = m0 * Hdim + ((blockIdx.x * blockDim.x + threadIdx.x) >> 5);
    const int lane = threadIdx.x & 31;
    const int b = row >> 9;

    const float f   = g_f[row];
    const float add = g_add[row];

    const float4* Cp = (const float4*)C_prev + (size_t)row * 128;
    float4*       Ct = (float4*)out_C       + (size_t)row * 128;
    const float4* qv = (const float4*)(g_q + b * Hdim);

    float acc = 0.f;
#pragma unroll
    for (int r = 0; r < 4; r++) {
        const int j = lane + 32 * r;
        const float4 c = __ldcs(&Cp[j]);
        const float4 q = qv[j];
        float4 t;
        t.x = f * c.x + add;
        t.y = f * c.y + add;
        t.z = f * c.z + add;
        t.w = f * c.w + add;
        __stcs(&Ct[j], t);
        acc += t.x * q.x;
        acc += t.y * q.y;
        acc += t.z * q.z;
        acc += t.w * q.w;
    }
#pragma unroll
    for (int off = 16; off; off >>= 1)
        acc += __shfl_xor_sync(0xffffffffu, acc, off);

    if (lane == 0)
        out_h[row] = g_o[row] * acc * g_rdenom[b];
}

// ---------------------------------------------------------------------------
// Launch: 2-chunk, 2-stream overlap. G1+K2_1 hide under K3_0.
// Inputs: x, h_prev(unused), C_prev, m_prev, n_prev, W, b
// Output: h_t[65536] | C_t[33554432] | m_t[65536] | n_t[65536]
// ---------------------------------------------------------------------------
extern "C" void kernel_launch(void* const* d_in, const int* in_sizes, int n_in,
                              void* d_out, int out_size)
{
    const float* x      = (const float*)d_in[0];
    const float* C_prev = (const float*)d_in[2];
    const float* m_prev = (const float*)d_in[3];
    const float* n_prev = (const float*)d_in[4];
    const float* W      = (const float*)d_in[5];
    const float* bias   = (const float*)d_in[6];

    float* out   = (float*)d_out;
    float* out_h = out;
    float* out_C = out + Bsz * Hdim;
    float* out_m = out_C + (size_t)Bsz * Hdim * Hdim;
    float* out_n = out_m + Bsz * Hdim;

    // One-time resource init (resources only; identical work every call).
    static cudaStream_t sA = nullptr, sB = nullptr;
    static cudaEvent_t ev0 = nullptr, evA0 = nullptr, evA1 = nullptr, evB = nullptr;
    if (sA == nullptr) {
        cudaStreamCreateWithFlags(&sA, cudaStreamNonBlocking);
        cudaStreamCreateWithFlags(&sB, cudaStreamNonBlocking);
        cudaEventCreateWithFlags(&ev0,  cudaEventDisableTiming);
        cudaEventCreateWithFlags(&evA0, cudaEventDisableTiming);
        cudaEventCreateWithFlags(&evA1, cudaEventDisableTiming);
        cudaEventCreateWithFlags(&evB,  cudaEventDisableTiming);
    }

    // Fork from the capture/launch stream.
    cudaEventRecord(ev0, 0);
    cudaStreamWaitEvent(sA, ev0, 0);

    // Stream A: the two GEMM halves.
    gemm_kernel<<<dim3(SIXH / BN, 1, KSPLIT), 128, 0, sA>>>(x, W, 0);
    cudaEventRecord(evA0, sA);
    gemm_kernel<<<dim3(SIXH / BN, 1, KSPLIT), 128, 0, sA>>>(x, W, MB);
    cudaEventRecord(evA1, sA);

    // Stream B: per-chunk epilogue; chunk 1's GEMM overlaps chunk 0's K3.
    cudaStreamWaitEvent(sB, evA0, 0);
    pointwise_kernel<<<MB, Hdim, 0, sB>>>(m_prev, n_prev, bias, out_m, out_n, 0);
    cupdate_kernel<<<(MB * Hdim) / 8, 256, 0, sB>>>(C_prev, out_C, out_h, 0);

    cudaStreamWaitEvent(sB, evA1, 0);
    pointwise_kernel<<<MB, Hdim, 0, sB>>>(m_prev, n_prev, bias, out_m, out_n, MB);
    cupdate_kernel<<<(MB * Hdim) / 8, 256, 0, sB>>>(C_prev, out_C, out_h, MB);

    // Join back into the launch stream.
    cudaEventRecord(evB, sB);
    cudaStreamWaitEvent(0, evB, 0);
}

// round 15
// speedup vs baseline: 1.0967x; 1.0967x over previous
#include <cuda_runtime.h>
#include <cuda_bf16.h>
#include <math.h>

// ---------------------------------------------------------------------------
// mLSTM cell — serial 3-kernel, full-batch, TM=8 GEMM.
// (Overlap abandoned: R7 and R11 both showed cross-stream chunk pipelines
//  serialize under graph capture and regress vs the serial schedule.)
//   K1: fp32 SIMT GEMM, split-K=8, BM=64/BN=64/BK=32, TM=8 x TN=4
//   K2: split-K sum + bias + pointwise gates -> m_t, n_t, scratch
//   K3: C_t = f*C_prev + add fused with Cq and h_t (single 268MB HBM pass)
// ---------------------------------------------------------------------------

#define Bsz 128
#define Hdim 512
#define SIXH 3072
#define INV_SQRT_H 0.044194173824159216f   // 1/sqrt(512)

#define KSPLIT 8
#define KCH    64                           // K per split (512/8)
#define GSTRIDE (Bsz * SIXH)                // 393216

// Scratch (device globals; no allocation allowed anywhere in this file)
__device__ float g_part[KSPLIT * GSTRIDE];  // 12.6 MB split-K partials
__device__ float g_f[Bsz * Hdim];
__device__ float g_add[Bsz * Hdim];
__device__ float g_o[Bsz * Hdim];
__device__ float g_q[Bsz * Hdim];
__device__ float g_rdenom[Bsz];

// ---------------------------------------------------------------------------
// Kernel 1: tiled fp32 GEMM, full batch, split-K=8 over grid.z.
// BM=64, BN=64, BK=32, 128 threads, TM=8 x TN=4 strided register tile.
// Per warp per 4-k sub-iter: 16 smem wavefronts vs 128 FFMA -> FMA-bound.
// grid = (48, 2, 8) = 768 blocks = 3072 warps.
// ---------------------------------------------------------------------------
#define BM 64
#define BN 64
#define BK 32

__global__ __launch_bounds__(128) void gemm_kernel(
    const float* __restrict__ X,      // [128, 512]
    const float* __restrict__ W)      // [3072, 512]
{
    __shared__ float As[BM][BK + 4];
    __shared__ float Bs[BN][BK + 4];

    const int tid = threadIdx.x;
    const int tm = tid >> 4;          // 0..7   (m = tm + 8r, r 0..7)
    const int tn = tid & 15;          // 0..15  (n = tn + 16s, s 0..3)
    const int bn = blockIdx.x * BN;
    const int bm = blockIdx.y * BM;
    const int kb = blockIdx.z * KCH;

    float acc[8][4];
#pragma unroll
    for (int r = 0; r < 8; r++)
#pragma unroll
        for (int s = 0; s < 4; s++) acc[r][s] = 0.f;

    const int lm = tid >> 3;          // 0..15 (load row)
    const int lk = (tid & 7) << 2;    // 0..28 step 4

#pragma unroll
    for (int k0 = 0; k0 < KCH; k0 += BK) {
        const int kabs = kb + k0 + lk;
        // A tile: 64x32 floats, 4 x float4 per thread
#pragma unroll
        for (int i = 0; i < 4; i++)
            *(float4*)&As[lm + 16 * i][lk] =
                *(const float4*)&X[(bm + lm + 16 * i) * 512 + kabs];
        // B tile: 64x32 floats, 4 x float4 per thread
#pragma unroll
        for (int i = 0; i < 4; i++)
            *(float4*)&Bs[lm + 16 * i][lk] =
                *(const float4*)&W[(bn + lm + 16 * i) * 512 + kabs];
        __syncthreads();

#pragma unroll
        for (int kk = 0; kk < BK; kk += 4) {
            float4 a[8], bq[4];
#pragma unroll
            for (int r = 0; r < 8; r++) a[r] = *(const float4*)&As[tm + 8 * r][kk];
#pragma unroll
            for (int s = 0; s < 4; s++) bq[s] = *(const float4*)&Bs[tn + 16 * s][kk];
#pragma unroll
            for (int r = 0; r < 8; r++)
#pragma unroll
                for (int s = 0; s < 4; s++) {
                    acc[r][s] += a[r].x * bq[s].x;
                    acc[r][s] += a[r].y * bq[s].y;
                    acc[r][s] += a[r].z * bq[s].z;
                    acc[r][s] += a[r].w * bq[s].w;
                }
        }
        __syncthreads();
    }

    float* gp = g_part + blockIdx.z * GSTRIDE;
#pragma unroll
    for (int r = 0; r < 8; r++) {
        const int m = bm + tm + 8 * r;
#pragma unroll
        for (int s = 0; s < 4; s++) {
            const int n = bn + tn + 16 * s;
            gp[m * SIXH + n] = acc[r][s];
        }
    }
}

// ---------------------------------------------------------------------------
// Kernel 2: split-K reduction + bias + pointwise gates + per-batch denom.
// One block per batch row (128 blocks). Deterministic fixed-order sum.
// ---------------------------------------------------------------------------
__global__ __launch_bounds__(512) void pointwise_kernel(
    const float* __restrict__ m_prev,
    const float* __restrict__ n_prev,
    const float* __restrict__ bias,
    float* __restrict__ out_m,
    float* __restrict__ out_n)
{
    __shared__ float red[512];
    const int b = blockIdx.x;
    const int h = threadIdx.x;

    float g[6];
#pragma unroll
    for (int gi = 0; gi < 6; gi++) {
        const int idx = b * SIXH + gi * Hdim + h;
        float acc = bias[gi * Hdim + h];
#pragma unroll
        for (int z = 0; z < KSPLIT; z++)
            acc += g_part[z * GSTRIDE + idx];
        g[gi] = acc;
    }
    const float ig = g[0], fg = g[1], og = g[2], qg = g[3], kg = g[4], vg = g[5];

    const int row = b * Hdim + h;
    const float mp = m_prev[row];
    const float np = n_prev[row];

    const float mt = fmaxf(fg + mp, ig);
    const float it = expf(ig - mt);
    const float ft = expf(fg + mp - mt);
    const float kt = INV_SQRT_H * kg;
    const float nt = ft * np + it * kt;
    const float ot = 1.f / (1.f + expf(-og));

    out_m[row] = mt;
    out_n[row] = nt;
    g_f[row]   = ft;
    g_add[row] = it * vg * kt;
    g_o[row]   = ot;
    g_q[row]   = qg;

    red[h] = nt * qg;
    __syncthreads();
#pragma unroll
    for (int s = 256; s > 0; s >>= 1) {
        if (h < s) red[h] += red[h + s];
        __syncthreads();
    }
    if (h == 0) g_rdenom[b] = 1.f / fmaxf(fabsf(red[0]), 1e-6f);
}

// ---------------------------------------------------------------------------
// Kernel 3: full-batch C update. One warp per (b,i) row of 512 floats.
// Streaming hints on C (zero reuse); q rows stay L2-resident (512x reuse).
// grid = 2048 blocks x 256 threads = 16384 warps.
// ---------------------------------------------------------------------------
__global__ __launch_bounds__(256) void cupdate_kernel(
    const float* __restrict__ C_prev,
    float* __restrict__ out_C,
    float* __restrict__ out_h)
{
    const int row  = (blockIdx.x * blockDim.x + threadIdx.x) >> 5;  // 0..16383
    const int lane = threadIdx.x & 31;
    const int b = row >> 9;

    const float f   = g_f[row];
    const float add = g_add[row];

    const float4* Cp = (const float4*)C_prev + (size_t)row * 128;
    float4*       Ct = (float4*)out_C       + (size_t)row * 128;
    const float4* qv = (const float4*)(g_q + b * Hdim);

    float acc = 0.f;
#pragma unroll
    for (int r = 0; r < 4; r++) {
        const int j = lane + 32 * r;
        const float4 c = __ldcs(&Cp[j]);
        const float4 q = qv[j];
        float4 t;
        t.x = f * c.x + add;
        t.y = f * c.y + add;
        t.z = f * c.z + add;
        t.w = f * c.w + add;
        __stcs(&Ct[j], t);
        acc += t.x * q.x;
        acc += t.y * q.y;
        acc += t.z * q.z;
        acc += t.w * q.w;
    }
#pragma unroll
    for (int off = 16; off; off >>= 1)
        acc += __shfl_xor_sync(0xffffffffu, acc, off);

    if (lane == 0)
        out_h[row] = g_o[row] * acc * g_rdenom[b];
}

// ---------------------------------------------------------------------------
// Launch: serial on the capture stream.
// Inputs: x, h_prev(unused), C_prev, m_prev, n_prev, W, b
// Output: h_t[65536] | C_t[33554432] | m_t[65536] | n_t[65536]
// ---------------------------------------------------------------------------
extern "C" void kernel_launch(void* const* d_in, const int* in_sizes, int n_in,
                              void* d_out, int out_size)
{
    const float* x      = (const float*)d_in[0];
    const float* C_prev = (const float*)d_in[2];
    const float* m_prev = (const float*)d_in[3];
    const float* n_prev = (const float*)d_in[4];
    const float* W      = (const float*)d_in[5];
    const float* bias   = (const float*)d_in[6];

    float* out   = (float*)d_out;
    float* out_h = out;
    float* out_C = out + Bsz * Hdim;
    float* out_m = out_C + (size_t)Bsz * Hdim * Hdim;
    float* out_n = out_m + Bsz * Hdim;

    gemm_kernel<<<dim3(SIXH / BN, Bsz / BM, KSPLIT), 128>>>(x, W);
    pointwise_kernel<<<Bsz, Hdim>>>(m_prev, n_prev, bias, out_m, out_n);
    cupdate_kernel<<<(Bsz * Hdim) / 8, 256>>>(C_prev, out_C, out_h);
}